// round 2
// baseline (speedup 1.0000x reference)
#include <cuda_runtime.h>
#include <cuda_bf16.h>

// ---------------------------------------------------------------------------
// Problem constants
// ---------------------------------------------------------------------------
#define BATCH 2048
#define ENS   32
#define WIN   10
#define DX    14
#define DZ    14
#define RAWD  22

#define BE        (BATCH * ENS)          // 65536
#define PM_IN     (WIN * DX)             // 140
#define SM_IN     (WIN * RAWD)           // 220

// Output regions (concatenated flattened tuple)
#define O1_OFF 0                          // state_corrected [B,E,DX]
#define O1_LEN (BATCH * ENS * DX)         // 917504
#define O2_OFF (O1_OFF + O1_LEN)          // state_corrected mean [B,1,DX]
#define O2_LEN (BATCH * DX)
#define O3_OFF (O2_OFF + O2_LEN)          // state_m [B,1,DX]
#define O3_LEN (BATCH * DX)
#define O4_OFF (O3_OFF + O3_LEN)          // z [B,1,DZ]
#define O4_LEN (BATCH * DZ)
#define O5_OFF (O4_OFF + O4_LEN)          // ensemble_z [B,E,DZ]
#define O5_LEN (BATCH * ENS * DZ)

// ---------------------------------------------------------------------------
// Scratch (device globals: no allocation allowed)
// ---------------------------------------------------------------------------
__device__ float g_h1[BE * 256];     // 67 MB
__device__ float g_h2[BE * 512];     // 134 MB
__device__ float g_pred[BE * DX];    // state_pred
__device__ float g_sens[BATCH * DZ]; // sensor MLP on distinct rows

// ---------------------------------------------------------------------------
// Tiled SGEMM with bias + optional leaky-relu.  C[M,N] = act(A[M,K]@B[K,N]+b)
// BM=128 BN=128 BK=8 TM=8 TN=8, 256 threads. M%BM==0, N%BN==0 assumed.
// ---------------------------------------------------------------------------
template <int BM, int BN, int BK, int TM, int TN, bool LEAKY>
__global__ void __launch_bounds__(256)
sgemm_bias_act(const float* __restrict__ A, const float* __restrict__ B,
               const float* __restrict__ bias, float* __restrict__ C,
               int M, int N, int K)
{
    constexpr int NT = (BM / TM) * (BN / TN);   // 256
    __shared__ __align__(16) float As[BK][BM];
    __shared__ __align__(16) float Bs[BK][BN];

    const int tid  = threadIdx.x;
    const int crow = blockIdx.y * BM;
    const int ccol = blockIdx.x * BN;
    const int tcol = (tid % (BN / TN)) * TN;
    const int trow = (tid / (BN / TN)) * TM;

    float acc[TM][TN];
#pragma unroll
    for (int i = 0; i < TM; i++)
#pragma unroll
        for (int j = 0; j < TN; j++) acc[i][j] = 0.f;

    for (int k0 = 0; k0 < K; k0 += BK) {
        // load A tile (BM x BK)
#pragma unroll
        for (int i = 0; i < BM * BK; i += NT) {
            int idx = i + tid;
            int m = idx / BK, kk = idx % BK;
            As[kk][m] = (k0 + kk < K) ? A[(size_t)(crow + m) * K + k0 + kk] : 0.f;
        }
        // load B tile (BK x BN)
#pragma unroll
        for (int i = 0; i < BK * BN; i += NT) {
            int idx = i + tid;
            int kk = idx / BN, n = idx % BN;
            Bs[kk][n] = (k0 + kk < K) ? B[(size_t)(k0 + kk) * N + ccol + n] : 0.f;
        }
        __syncthreads();

#pragma unroll
        for (int kk = 0; kk < BK; kk++) {
            float ra[TM], rb[TN];
#pragma unroll
            for (int i = 0; i < TM; i += 4) {
                float4 v = *(const float4*)&As[kk][trow + i];
                ra[i] = v.x; ra[i + 1] = v.y; ra[i + 2] = v.z; ra[i + 3] = v.w;
            }
#pragma unroll
            for (int j = 0; j < TN; j += 4) {
                float4 v = *(const float4*)&Bs[kk][tcol + j];
                rb[j] = v.x; rb[j + 1] = v.y; rb[j + 2] = v.z; rb[j + 3] = v.w;
            }
#pragma unroll
            for (int i = 0; i < TM; i++)
#pragma unroll
                for (int j = 0; j < TN; j++) acc[i][j] += ra[i] * rb[j];
        }
        __syncthreads();
    }

#pragma unroll
    for (int i = 0; i < TM; i++) {
#pragma unroll
        for (int j = 0; j < TN; j++) {
            float v = acc[i][j] + bias[ccol + tcol + j];
            if (LEAKY) v = (v >= 0.f) ? v : 0.01f * v;
            C[(size_t)(crow + trow + i) * N + ccol + tcol + j] = v;
        }
    }
}

// ---------------------------------------------------------------------------
// PM stage 3: pred[M,14] = h2[M,512] @ W[512,14] + b.  One warp per row.
// ---------------------------------------------------------------------------
__global__ void __launch_bounds__(256)
pm_out_kernel(const float* __restrict__ h2, const float* __restrict__ W,
              const float* __restrict__ bias, float* __restrict__ pred)
{
    __shared__ float Ws[512 * DX];
    __shared__ float bs[DX];
    const int tid = threadIdx.x;
    for (int i = tid; i < 512 * DX; i += 256) Ws[i] = W[i];
    if (tid < DX) bs[tid] = bias[tid];
    __syncthreads();

    const int warp = tid >> 5, lane = tid & 31;
    const int row = blockIdx.x * 8 + warp;
    const float* hrow = h2 + (size_t)row * 512;

    float h[16];
#pragma unroll
    for (int i = 0; i < 16; i++) h[i] = hrow[lane + 32 * i];

    float out[DX];
#pragma unroll
    for (int c = 0; c < DX; c++) {
        float acc = 0.f;
#pragma unroll
        for (int i = 0; i < 16; i++) acc += h[i] * Ws[(lane + 32 * i) * DX + c];
#pragma unroll
        for (int off = 16; off > 0; off >>= 1) acc += __shfl_xor_sync(0xFFFFFFFFu, acc, off);
        out[c] = acc;
    }
    if (lane == 0) {
#pragma unroll
        for (int c = 0; c < DX; c++) pred[(size_t)row * DX + c] = out[c] + bs[c];
    }
}

// ---------------------------------------------------------------------------
// Sensor MLP on the 2048 DISTINCT raw_obs rows: 220->256->256->64->14.
// 8 rows per block, 256 threads (thread = output column).
// ---------------------------------------------------------------------------
__global__ void __launch_bounds__(256)
sensor_kernel(const float* __restrict__ raw,
              const float* __restrict__ w2, const float* __restrict__ b2,
              const float* __restrict__ w3, const float* __restrict__ b3,
              const float* __restrict__ w5, const float* __restrict__ b5,
              const float* __restrict__ w6, const float* __restrict__ b6,
              float* __restrict__ sens)
{
    __shared__ float s[8][SM_IN];
    __shared__ float h1[8][256];
    __shared__ float h2[8][256];
    __shared__ float h3[8][64];

    const int tid = threadIdx.x;
    const int row0 = blockIdx.x * 8;

    for (int i = tid; i < 8 * SM_IN; i += 256) {
        int r = i / SM_IN, k = i % SM_IN;
        s[r][k] = raw[(size_t)(row0 + r) * SM_IN + k];
    }
    __syncthreads();

    {   // layer 1: 220 -> 256, leaky
        float acc[8];
#pragma unroll
        for (int r = 0; r < 8; r++) acc[r] = b2[tid];
        for (int k = 0; k < SM_IN; k++) {
            float w = w2[k * 256 + tid];
#pragma unroll
            for (int r = 0; r < 8; r++) acc[r] += s[r][k] * w;
        }
#pragma unroll
        for (int r = 0; r < 8; r++) {
            float v = acc[r];
            h1[r][tid] = (v >= 0.f) ? v : 0.01f * v;
        }
    }
    __syncthreads();

    {   // layer 2: 256 -> 256, leaky
        float acc[8];
#pragma unroll
        for (int r = 0; r < 8; r++) acc[r] = b3[tid];
        for (int k = 0; k < 256; k++) {
            float w = w3[k * 256 + tid];
#pragma unroll
            for (int r = 0; r < 8; r++) acc[r] += h1[r][k] * w;
        }
#pragma unroll
        for (int r = 0; r < 8; r++) {
            float v = acc[r];
            h2[r][tid] = (v >= 0.f) ? v : 0.01f * v;
        }
    }
    __syncthreads();

    if (tid < 64) {  // layer 3: 256 -> 64, leaky
        float acc[8];
#pragma unroll
        for (int r = 0; r < 8; r++) acc[r] = b5[tid];
        for (int k = 0; k < 256; k++) {
            float w = w5[k * 64 + tid];
#pragma unroll
            for (int r = 0; r < 8; r++) acc[r] += h2[r][k] * w;
        }
#pragma unroll
        for (int r = 0; r < 8; r++) {
            float v = acc[r];
            h3[r][tid] = (v >= 0.f) ? v : 0.01f * v;
        }
    }
    __syncthreads();

    if (tid < DZ) {  // layer 4: 64 -> 14, linear
        float acc[8];
#pragma unroll
        for (int r = 0; r < 8; r++) acc[r] = b6[tid];
        for (int k = 0; k < 64; k++) {
            float w = w6[k * DZ + tid];
#pragma unroll
            for (int r = 0; r < 8; r++) acc[r] += h3[r][k] * w;
        }
#pragma unroll
        for (int r = 0; r < 8; r++) sens[(size_t)(row0 + r) * DZ + tid] = acc[r];
    }
}

// ---------------------------------------------------------------------------
// EnKF correction per batch element. One CTA (256 threads) per b.
// ---------------------------------------------------------------------------
__global__ void __launch_bounds__(256)
enkf_kernel(const float* __restrict__ pred_g, const float* __restrict__ sens,
            const float* __restrict__ on_w1, const float* __restrict__ on_b1,
            const float* __restrict__ on_w2, const float* __restrict__ on_b2,
            float* __restrict__ out1, float* __restrict__ out2,
            float* __restrict__ out3, float* __restrict__ out4,
            float* __restrict__ out5)
{
    const int b = blockIdx.x;
    const int tid = threadIdx.x;

    __shared__ float pred[ENS][DX], ez[ENS][DZ], Am[ENS][DX], corr[ENS][DX];
    __shared__ float sm[DX], zm[DZ], rdiag[DZ], hid[32];
    __shared__ float Mm[DX][DX];
    __shared__ float Km[DX][DZ];
    __shared__ float aug[DX][2 * DX];
    __shared__ float fac[DX];

    // load state_pred rows and ensemble_z (gather with the tile/reshape aliasing)
    for (int i = tid; i < ENS * DX; i += 256) {
        pred[i / DX][i % DX] = pred_g[(size_t)b * ENS * DX + i];
    }
    for (int i = tid; i < ENS * DZ; i += 256) {
        int e = i / DZ, j = i % DZ;
        int src = (b * ENS + e) % BATCH;
        float v = sens[src * DZ + j];
        ez[e][j] = v;
        out5[(size_t)(b * ENS + e) * DZ + j] = v;
    }
    __syncthreads();

    if (tid < DX) {
        float s1 = 0.f, s2 = 0.f;
        for (int e = 0; e < ENS; e++) { s1 += pred[e][tid]; s2 += ez[e][tid]; }
        float m1 = s1 * (1.f / ENS), m2 = s2 * (1.f / ENS);
        sm[tid] = m1; zm[tid] = m2;
        out3[b * DX + tid] = m1;
        out4[b * DZ + tid] = m2;
    }
    __syncthreads();

    // observation noise R = diag( (relu(z@W1+b1)@W2+b2 + 1e-3)^2 + 0.038729833 )
    if (tid < 32) {
        float a = on_b1[tid];
        for (int i = 0; i < DZ; i++) a += zm[i] * on_w1[i * 32 + tid];
        hid[tid] = (a > 0.f) ? a : 0.f;
    }
    __syncthreads();
    if (tid < DZ) {
        float a = on_b2[tid];
        for (int j = 0; j < 32; j++) a += hid[j] * on_w2[j * DZ + tid];
        a += 0.001f;
        rdiag[tid] = a * a + 0.038729833f;
    }
    // anomalies
    for (int i = tid; i < ENS * DX; i += 256) {
        int e = i / DX, j = i % DX;
        Am[e][j] = pred[e][j] - sm[j];
    }
    __syncthreads();

    // S/(E-1) and augmented [innovation | I]
    if (tid < DX * DX) {
        int i = tid / DX, j = tid % DX;
        float s = 0.f;
        for (int e = 0; e < ENS; e++) s += Am[e][i] * Am[e][j];
        float m = s * (1.f / (ENS - 1));
        Mm[i][j] = m;
        aug[i][j] = m + ((i == j) ? rdiag[i] : 0.f);
        aug[i][DX + j] = (i == j) ? 1.f : 0.f;
    }
    __syncthreads();

    // Gauss-Jordan (SPD -> no pivoting needed)
    for (int p = 0; p < DX; p++) {
        float pv = aug[p][p];            // all threads read before anyone writes
        __syncthreads();
        if (tid < 2 * DX) aug[p][tid] *= (1.f / pv);
        if (tid < DX) fac[tid] = (tid == p) ? 0.f : aug[tid][p];
        __syncthreads();
        for (int t = tid; t < DX * 2 * DX; t += 256) {
            int r = t / (2 * DX), c = t % (2 * DX);
            if (r != p) aug[r][c] -= fac[r] * aug[p][c];
        }
        __syncthreads();
    }

    // K = (S/(E-1)) @ inv(innovation)
    if (tid < DX * DX) {
        int i = tid / DX, j = tid % DX;
        float s = 0.f;
        for (int k = 0; k < DX; k++) s += Mm[i][k] * aug[k][DX + j];
        Km[i][j] = s;
    }
    __syncthreads();

    // gain + corrected state
    for (int t = tid; t < ENS * DX; t += 256) {
        int e = t / DX, i = t % DX;
        float s = pred[e][i];
        for (int j = 0; j < DZ; j++) s += Km[i][j] * (ez[e][j] - pred[e][j]);
        corr[e][i] = s;
        out1[(size_t)(b * ENS + e) * DX + i] = s;
    }
    __syncthreads();
    if (tid < DX) {
        float s = 0.f;
        for (int e = 0; e < ENS; e++) s += corr[e][tid];
        out2[b * DX + tid] = s * (1.f / ENS);
    }
}

// ---------------------------------------------------------------------------
// Launcher
// ---------------------------------------------------------------------------
extern "C" void kernel_launch(void* const* d_in, const int* in_sizes, int n_in,
                              void* d_out, int out_size)
{
    const float* raw      = (const float*)d_in[0];
    const float* sp       = (const float*)d_in[1];
    const float* pm_w1    = (const float*)d_in[2];
    const float* pm_b1    = (const float*)d_in[3];
    const float* pm_w3    = (const float*)d_in[4];
    const float* pm_b3    = (const float*)d_in[5];
    const float* pm_wm2   = (const float*)d_in[6];
    const float* pm_bm2   = (const float*)d_in[7];
    const float* sm_w2    = (const float*)d_in[8];
    const float* sm_b2    = (const float*)d_in[9];
    const float* sm_w3    = (const float*)d_in[10];
    const float* sm_b3    = (const float*)d_in[11];
    const float* sm_w5    = (const float*)d_in[12];
    const float* sm_b5    = (const float*)d_in[13];
    const float* sm_w6    = (const float*)d_in[14];
    const float* sm_b6    = (const float*)d_in[15];
    const float* on_w1    = (const float*)d_in[16];
    const float* on_b1    = (const float*)d_in[17];
    const float* on_w2    = (const float*)d_in[18];
    const float* on_b2    = (const float*)d_in[19];

    float* out = (float*)d_out;
    float* out1 = out + O1_OFF;
    float* out2 = out + O2_OFF;
    float* out3 = out + O3_OFF;
    float* out4 = out + O4_OFF;
    float* out5 = out + O5_OFF;

    float *h1p, *h2p, *predp, *sensp;
    cudaGetSymbolAddress((void**)&h1p,   g_h1);
    cudaGetSymbolAddress((void**)&h2p,   g_h2);
    cudaGetSymbolAddress((void**)&predp, g_pred);
    cudaGetSymbolAddress((void**)&sensp, g_sens);

    // Process model: 140 -> 256 -> 512 -> 14
    sgemm_bias_act<128, 128, 8, 8, 8, true>
        <<<dim3(256 / 128, BE / 128), 256>>>(sp, pm_w1, pm_b1, h1p, BE, 256, PM_IN);
    sgemm_bias_act<128, 128, 8, 8, 8, true>
        <<<dim3(512 / 128, BE / 128), 256>>>(h1p, pm_w3, pm_b3, h2p, BE, 512, 256);
    pm_out_kernel<<<BE / 8, 256>>>(h2p, pm_wm2, pm_bm2, predp);

    // Sensor model on distinct rows only (tile aliasing exploited)
    sensor_kernel<<<BATCH / 8, 256>>>(raw, sm_w2, sm_b2, sm_w3, sm_b3,
                                      sm_w5, sm_b5, sm_w6, sm_b6, sensp);

    // EnKF correction + all outputs
    enkf_kernel<<<BATCH, 256>>>(predp, sensp, on_w1, on_b1, on_w2, on_b2,
                                out1, out2, out3, out4, out5);
}

// round 4
// speedup vs baseline: 2.1135x; 2.1135x over previous
#include <cuda_runtime.h>
#include <cuda_bf16.h>
#include <cstdint>

#define BATCH 2048
#define ENS   32
#define DX    14
#define DZ    14
#define PM_IN 140
#define SM_IN 220
#define BE    (BATCH * ENS)

#define O1_OFF 0
#define O2_OFF (BATCH * ENS * DX)
#define O3_OFF (O2_OFF + BATCH * DX)
#define O4_OFF (O3_OFF + BATCH * DX)
#define O5_OFF (O4_OFF + BATCH * DZ)

// ---------------- scratch globals (uint32 = packed bf16 pair) ----------------
__device__ uint32_t g_xh [(size_t)BE * 96];    // x hi  [BE][192] bf16
__device__ uint32_t g_xl [(size_t)BE * 96];
__device__ uint32_t g_w1h[256 * 96];           // w1^T  [256][192]
__device__ uint32_t g_w1l[256 * 96];
__device__ uint32_t g_w3h[512 * 128];          // w3^T  [512][256]
__device__ uint32_t g_w3l[512 * 128];
__device__ uint32_t g_h1h[(size_t)BE * 128];   // h1    [BE][256]
__device__ uint32_t g_h1l[(size_t)BE * 128];
__device__ float    g_part[(size_t)8 * BE * DX];
__device__ float    g_sens[BATCH * DZ];

// ---------------- helpers ----------------
__device__ __forceinline__ uint32_t smem_u32(const void* p) {
    uint32_t a;
    asm("{ .reg .u64 t; cvta.to.shared.u64 t, %1; cvt.u32.u64 %0, t; }" : "=r"(a) : "l"(p));
    return a;
}
#define CP16(d, s) asm volatile("cp.async.cg.shared.global [%0], [%1], 16;" :: "r"(d), "l"(s))
#define CP_COMMIT() asm volatile("cp.async.commit_group;")
#define CP_WAIT()   asm volatile("cp.async.wait_group 0;" ::: "memory")

__device__ __forceinline__ void ldsm4(uint32_t (&r)[4], uint32_t addr) {
    asm volatile("ldmatrix.sync.aligned.m8n8.x4.shared.b16 {%0,%1,%2,%3}, [%4];"
                 : "=r"(r[0]), "=r"(r[1]), "=r"(r[2]), "=r"(r[3]) : "r"(addr));
}
__device__ __forceinline__ void mma_bf16(float (&d)[4], const uint32_t (&a)[4],
                                         uint32_t b0, uint32_t b1) {
    asm volatile(
        "mma.sync.aligned.m16n8k16.row.col.f32.bf16.bf16.f32 "
        "{%0,%1,%2,%3}, {%4,%5,%6,%7}, {%8,%9}, {%0,%1,%2,%3};"
        : "+f"(d[0]), "+f"(d[1]), "+f"(d[2]), "+f"(d[3])
        : "r"(a[0]), "r"(a[1]), "r"(a[2]), "r"(a[3]), "r"(b0), "r"(b1));
}
__device__ __forceinline__ void split2(float v0, float v1, uint32_t& hi, uint32_t& lo) {
    __nv_bfloat16 h0 = __float2bfloat16(v0), h1 = __float2bfloat16(v1);
    __nv_bfloat16 g0 = __float2bfloat16(v0 - __bfloat162float(h0));
    __nv_bfloat16 g1 = __float2bfloat16(v1 - __bfloat162float(h1));
    hi = (uint32_t)__bfloat16_as_ushort(h0) | ((uint32_t)__bfloat16_as_ushort(h1) << 16);
    lo = (uint32_t)__bfloat16_as_ushort(g0) | ((uint32_t)__bfloat16_as_ushort(g1) << 16);
}

// ---------------- prep: x -> hi/lo bf16, K padded to 192 ----------------
__global__ void __launch_bounds__(256)
prep_x_kernel(const float* __restrict__ x)
{
    int idx = blockIdx.x * 256 + threadIdx.x;   // BE*96
    int row = idx / 96, p = idx % 96, k = 2 * p;
    float v0 = (k < PM_IN) ? x[(size_t)row * PM_IN + k] : 0.f;
    float v1 = (k + 1 < PM_IN) ? x[(size_t)row * PM_IN + k + 1] : 0.f;
    uint32_t hi, lo;
    split2(v0, v1, hi, lo);
    g_xh[(size_t)row * 96 + p] = hi;
    g_xl[(size_t)row * 96 + p] = lo;
}

// ---------------- prep: weights transposed -> hi/lo bf16 ----------------
__global__ void __launch_bounds__(256)
prep_w_kernel(const float* __restrict__ w1, const float* __restrict__ w3)
{
    int idx = blockIdx.x * 256 + threadIdx.x;
    uint32_t hi, lo;
    if (idx < 256 * 96) {                        // w1 [140][256] -> [256][192]
        int n = idx / 96, p = idx % 96, k = 2 * p;
        float v0 = (k < PM_IN) ? w1[(size_t)k * 256 + n] : 0.f;
        float v1 = (k + 1 < PM_IN) ? w1[(size_t)(k + 1) * 256 + n] : 0.f;
        split2(v0, v1, hi, lo);
        g_w1h[idx] = hi; g_w1l[idx] = lo;
    } else if (idx < 256 * 96 + 512 * 128) {     // w3 [256][512] -> [512][256]
        int i2 = idx - 256 * 96;
        int n = i2 / 128, p = i2 % 128, k = 2 * p;
        split2(w3[(size_t)k * 512 + n], w3[(size_t)(k + 1) * 512 + n], hi, lo);
        g_w3h[i2] = hi; g_w3l[i2] = lo;
    }
}

// ---------------- HMMA split-bf16 GEMM ----------------
// C-tile 128x128, BK=64, 8 warps (4x2), warp tile 32x64.
// EPI=0: h1 = leaky(acc+bias) split -> g_h1h/g_h1l
// EPI=1: fused wm2 projection -> g_part (8 slices)
template <int KCHUNKS, int EPI>
__global__ void __launch_bounds__(256, 1)
gemm_hmma(const uint32_t* __restrict__ Ah, const uint32_t* __restrict__ Al,
          const uint32_t* __restrict__ Bh, const uint32_t* __restrict__ Bl,
          int kstr,                             // row stride in uint32 (Kpad/2)
          const float* __restrict__ bias, const float* __restrict__ wm2)
{
    extern __shared__ char smem[];
    const uint32_t ub = smem_u32(smem);
    float* biasS = (float*)(smem + 65536);
    float* wm2s  = (float*)(smem + 66048);

    const int tid = threadIdx.x, wid = tid >> 5, lane = tid & 31;
    const int bn = blockIdx.x, bt = blockIdx.y;
    const int mw = (wid >> 1) * 32;              // warp m offset
    const int nw = (wid & 1) * 64;               // warp n offset

    if (tid < 128) biasS[tid] = bias[bn * 128 + tid];
    if (EPI == 1) {
        for (int i = tid; i < 128 * DX; i += 256) {
            int c = i / DX, m = i % DX;
            wm2s[c * 16 + m] = wm2[(size_t)(bn * 128 + c) * DX + m];
        }
    }

    float acc[2][8][4];
#pragma unroll
    for (int f = 0; f < 2; f++)
#pragma unroll
        for (int g = 0; g < 8; g++)
#pragma unroll
            for (int e = 0; e < 4; e++) acc[f][g][e] = 0.f;

#pragma unroll 1
    for (int kc = 0; kc < KCHUNKS; kc++) {
        __syncthreads();
        // load 4 tiles of 128x64 bf16 (16KB each): Ah, Al, Bh, Bl
#pragma unroll
        for (int i = tid; i < 4096; i += 256) {
            int t = i >> 10, r = (i >> 3) & 127, c = i & 7;
            const uint32_t* gp;
            int grow;
            if (t == 0)      { gp = Ah; grow = bt * 128 + r; }
            else if (t == 1) { gp = Al; grow = bt * 128 + r; }
            else if (t == 2) { gp = Bh; grow = bn * 128 + r; }
            else             { gp = Bl; grow = bn * 128 + r; }
            const uint32_t* src = gp + (size_t)grow * kstr + kc * 32 + c * 4;
            uint32_t dst = ub + t * 16384 + r * 128 + ((c * 16) ^ ((r & 7) << 4));
            CP16(dst, src);
        }
        CP_COMMIT(); CP_WAIT();
        __syncthreads();

#pragma unroll
        for (int k16 = 0; k16 < 4; k16++) {
            uint32_t ah[2][4], al[2][4];
#pragma unroll
            for (int f = 0; f < 2; f++) {
                int mrow = mw + f * 16 + (lane & 15);
                int cb = k16 * 32 + ((lane >> 4) << 4);
                uint32_t off = mrow * 128 + (cb ^ ((mrow & 7) << 4));
                ldsm4(ah[f], ub + off);
                ldsm4(al[f], ub + 16384 + off);
            }
            uint32_t bh[4][4], bl[4][4];
#pragma unroll
            for (int g = 0; g < 4; g++) {
                int nrow = nw + g * 16 + ((lane >> 4) << 3) + (lane & 7);
                int cb = k16 * 32 + (((lane >> 3) & 1) << 4);
                uint32_t off = nrow * 128 + (cb ^ ((nrow & 7) << 4));
                ldsm4(bh[g], ub + 32768 + off);
                ldsm4(bl[g], ub + 49152 + off);
            }
#pragma unroll
            for (int f = 0; f < 2; f++)
#pragma unroll
                for (int g = 0; g < 4; g++) {
                    mma_bf16(acc[f][2 * g],     ah[f], bh[g][0], bh[g][1]);
                    mma_bf16(acc[f][2 * g],     ah[f], bl[g][0], bl[g][1]);
                    mma_bf16(acc[f][2 * g],     al[f], bh[g][0], bh[g][1]);
                    mma_bf16(acc[f][2 * g + 1], ah[f], bh[g][2], bh[g][3]);
                    mma_bf16(acc[f][2 * g + 1], ah[f], bl[g][2], bl[g][3]);
                    mma_bf16(acc[f][2 * g + 1], al[f], bh[g][2], bh[g][3]);
                }
        }
    }
    __syncthreads();

    if (EPI == 0) {
        // h1 = leaky(acc + bias), split to hi/lo, packed pair writes
#pragma unroll
        for (int f = 0; f < 2; f++) {
            int row0 = bt * 128 + mw + f * 16 + (lane >> 2);
#pragma unroll
            for (int nf = 0; nf < 8; nf++) {
                int col = nw + nf * 8 + 2 * (lane & 3);
                float b0 = biasS[col], b1 = biasS[col + 1];
                float v0 = acc[f][nf][0] + b0, v1 = acc[f][nf][1] + b1;
                float v2 = acc[f][nf][2] + b0, v3 = acc[f][nf][3] + b1;
                v0 = v0 >= 0.f ? v0 : 0.01f * v0;
                v1 = v1 >= 0.f ? v1 : 0.01f * v1;
                v2 = v2 >= 0.f ? v2 : 0.01f * v2;
                v3 = v3 >= 0.f ? v3 : 0.01f * v3;
                uint32_t hi, lo;
                int gcol = bn * 128 + col;
                split2(v0, v1, hi, lo);
                g_h1h[(size_t)row0 * 128 + gcol / 2] = hi;
                g_h1l[(size_t)row0 * 128 + gcol / 2] = lo;
                split2(v2, v3, hi, lo);
                g_h1h[(size_t)(row0 + 8) * 128 + gcol / 2] = hi;
                g_h1l[(size_t)(row0 + 8) * 128 + gcol / 2] = lo;
            }
        }
    } else {
        // fused projection: proj[slot][m] = sum_c leaky(acc+b3)[c] * wm2[c][m]
        float proj[4][DX];
#pragma unroll
        for (int s = 0; s < 4; s++)
#pragma unroll
            for (int m = 0; m < DX; m++) proj[s][m] = 0.f;
#pragma unroll
        for (int f = 0; f < 2; f++)
#pragma unroll
            for (int nf = 0; nf < 8; nf++) {
                int col = nw + nf * 8 + 2 * (lane & 3);
#pragma unroll
                for (int e = 0; e < 2; e++) {
                    int c = col + e;
                    float b = biasS[c];
                    float v0 = acc[f][nf][e] + b;
                    float v1 = acc[f][nf][2 + e] + b;
                    v0 = v0 >= 0.f ? v0 : 0.01f * v0;
                    v1 = v1 >= 0.f ? v1 : 0.01f * v1;
                    const float* wr = wm2s + c * 16;
#pragma unroll
                    for (int m = 0; m < DX; m++) {
                        float wv = wr[m];
                        proj[2 * f][m]     += v0 * wv;
                        proj[2 * f + 1][m] += v1 * wv;
                    }
                }
            }
        // reduce across the quad (lanes differing in t%4 hold different cols)
#pragma unroll
        for (int s = 0; s < 4; s++)
#pragma unroll
            for (int m = 0; m < DX; m++) {
                proj[s][m] += __shfl_xor_sync(0xFFFFFFFFu, proj[s][m], 1);
                proj[s][m] += __shfl_xor_sync(0xFFFFFFFFu, proj[s][m], 2);
            }
        if ((lane & 3) == 0) {
            int slice = bn * 2 + (wid & 1);
#pragma unroll
            for (int s = 0; s < 4; s++) {
                int row = bt * 128 + mw + (s >> 1) * 16 + (lane >> 2) + (s & 1) * 8;
                float* dst = g_part + ((size_t)slice * BE + row) * DX;
#pragma unroll
                for (int m = 0; m < DX; m++) dst[m] = proj[s][m];
            }
        }
    }
}

// ---------------- sensor MLP on 2048 distinct rows ----------------
__global__ void __launch_bounds__(256)
sensor_kernel(const float* __restrict__ raw,
              const float* __restrict__ w2, const float* __restrict__ b2,
              const float* __restrict__ w3, const float* __restrict__ b3,
              const float* __restrict__ w5, const float* __restrict__ b5,
              const float* __restrict__ w6, const float* __restrict__ b6,
              float* __restrict__ sens)
{
    __shared__ float s[4][SM_IN], h1[4][256], h2[4][256], h3[4][64];
    const int tid = threadIdx.x;
    const int row0 = blockIdx.x * 4;

    for (int i = tid; i < 4 * SM_IN; i += 256)
        s[i / SM_IN][i % SM_IN] = raw[(size_t)(row0 + i / SM_IN) * SM_IN + i % SM_IN];
    __syncthreads();
    {
        float acc[4];
#pragma unroll
        for (int r = 0; r < 4; r++) acc[r] = b2[tid];
        for (int k = 0; k < SM_IN; k++) {
            float w = w2[k * 256 + tid];
#pragma unroll
            for (int r = 0; r < 4; r++) acc[r] += s[r][k] * w;
        }
#pragma unroll
        for (int r = 0; r < 4; r++) h1[r][tid] = acc[r] >= 0.f ? acc[r] : 0.01f * acc[r];
    }
    __syncthreads();
    {
        float acc[4];
#pragma unroll
        for (int r = 0; r < 4; r++) acc[r] = b3[tid];
        for (int k = 0; k < 256; k++) {
            float w = w3[k * 256 + tid];
#pragma unroll
            for (int r = 0; r < 4; r++) acc[r] += h1[r][k] * w;
        }
#pragma unroll
        for (int r = 0; r < 4; r++) h2[r][tid] = acc[r] >= 0.f ? acc[r] : 0.01f * acc[r];
    }
    __syncthreads();
    if (tid < 64) {
        float acc[4];
#pragma unroll
        for (int r = 0; r < 4; r++) acc[r] = b5[tid];
        for (int k = 0; k < 256; k++) {
            float w = w5[k * 64 + tid];
#pragma unroll
            for (int r = 0; r < 4; r++) acc[r] += h2[r][k] * w;
        }
#pragma unroll
        for (int r = 0; r < 4; r++) h3[r][tid] = acc[r] >= 0.f ? acc[r] : 0.01f * acc[r];
    }
    __syncthreads();
    if (tid < DZ) {
        float acc[4];
#pragma unroll
        for (int r = 0; r < 4; r++) acc[r] = b6[tid];
        for (int k = 0; k < 64; k++) {
            float w = w6[k * DZ + tid];
#pragma unroll
            for (int r = 0; r < 4; r++) acc[r] += h3[r][k] * w;
        }
#pragma unroll
        for (int r = 0; r < 4; r++) sens[(size_t)(row0 + r) * DZ + tid] = acc[r];
    }
}

// ---------------- EnKF per batch element ----------------
__global__ void __launch_bounds__(256)
enkf_kernel(const float* __restrict__ part, const float* __restrict__ pm_bm2,
            const float* __restrict__ sens,
            const float* __restrict__ on_w1, const float* __restrict__ on_b1,
            const float* __restrict__ on_w2, const float* __restrict__ on_b2,
            float* __restrict__ out1, float* __restrict__ out2,
            float* __restrict__ out3, float* __restrict__ out4,
            float* __restrict__ out5)
{
    const int b = blockIdx.x, tid = threadIdx.x;
    __shared__ float pred[ENS][DX], ez[ENS][DZ], Am[ENS][DX], corr[ENS][DX];
    __shared__ float sm[DX], zm[DZ], rdiag[DZ], hid[32];
    __shared__ float Mm[DX][DX], Km[DX][DZ], aug[DX][2 * DX], fac[DX];

    for (int i = tid; i < ENS * DX; i += 256) {
        int e = i / DX, j = i % DX;
        size_t row = (size_t)b * ENS + e;
        float p = pm_bm2[j];
#pragma unroll
        for (int q = 0; q < 8; q++) p += part[((size_t)q * BE + row) * DX + j];
        pred[e][j] = p;
    }
    for (int i = tid; i < ENS * DZ; i += 256) {
        int e = i / DZ, j = i % DZ;
        int src = (b * ENS + e) % BATCH;
        float v = sens[src * DZ + j];
        ez[e][j] = v;
        out5[(size_t)(b * ENS + e) * DZ + j] = v;
    }
    __syncthreads();
    if (tid < DX) {
        float s1 = 0.f, s2 = 0.f;
        for (int e = 0; e < ENS; e++) { s1 += pred[e][tid]; s2 += ez[e][tid]; }
        float m1 = s1 * (1.f / ENS), m2 = s2 * (1.f / ENS);
        sm[tid] = m1; zm[tid] = m2;
        out3[b * DX + tid] = m1;
        out4[b * DZ + tid] = m2;
    }
    __syncthreads();
    if (tid < 32) {
        float a = on_b1[tid];
        for (int i = 0; i < DZ; i++) a += zm[i] * on_w1[i * 32 + tid];
        hid[tid] = a > 0.f ? a : 0.f;
    }
    __syncthreads();
    if (tid < DZ) {
        float a = on_b2[tid];
        for (int j = 0; j < 32; j++) a += hid[j] * on_w2[j * DZ + tid];
        a += 0.001f;
        rdiag[tid] = a * a + 0.038729833f;
    }
    for (int i = tid; i < ENS * DX; i += 256)
        Am[i / DX][i % DX] = pred[i / DX][i % DX] - sm[i % DX];
    __syncthreads();
    if (tid < DX * DX) {
        int i = tid / DX, j = tid % DX;
        float s = 0.f;
        for (int e = 0; e < ENS; e++) s += Am[e][i] * Am[e][j];
        float m = s * (1.f / (ENS - 1));
        Mm[i][j] = m;
        aug[i][j] = m + (i == j ? rdiag[i] : 0.f);
        aug[i][DX + j] = (i == j) ? 1.f : 0.f;
    }
    __syncthreads();
    for (int p = 0; p < DX; p++) {
        float pv = aug[p][p];
        __syncthreads();
        if (tid < 2 * DX) aug[p][tid] *= (1.f / pv);
        if (tid < DX) fac[tid] = (tid == p) ? 0.f : aug[tid][p];
        __syncthreads();
        for (int t = tid; t < DX * 2 * DX; t += 256) {
            int rr = t / (2 * DX), c = t % (2 * DX);
            if (rr != p) aug[rr][c] -= fac[rr] * aug[p][c];
        }
        __syncthreads();
    }
    if (tid < DX * DX) {
        int i = tid / DX, j = tid % DX;
        float s = 0.f;
        for (int k = 0; k < DX; k++) s += Mm[i][k] * aug[k][DX + j];
        Km[i][j] = s;
    }
    __syncthreads();
    for (int t = tid; t < ENS * DX; t += 256) {
        int e = t / DX, i = t % DX;
        float s = pred[e][i];
        for (int j = 0; j < DZ; j++) s += Km[i][j] * (ez[e][j] - pred[e][j]);
        corr[e][i] = s;
        out1[(size_t)(b * ENS + e) * DX + i] = s;
    }
    __syncthreads();
    if (tid < DX) {
        float s = 0.f;
        for (int e = 0; e < ENS; e++) s += corr[e][tid];
        out2[b * DX + tid] = s * (1.f / ENS);
    }
}

// ---------------- launcher ----------------
extern "C" void kernel_launch(void* const* d_in, const int* in_sizes, int n_in,
                              void* d_out, int out_size)
{
    const float* raw    = (const float*)d_in[0];
    const float* sp     = (const float*)d_in[1];
    const float* pm_w1  = (const float*)d_in[2];
    const float* pm_b1  = (const float*)d_in[3];
    const float* pm_w3  = (const float*)d_in[4];
    const float* pm_b3  = (const float*)d_in[5];
    const float* pm_wm2 = (const float*)d_in[6];
    const float* pm_bm2 = (const float*)d_in[7];
    const float* sm_w2  = (const float*)d_in[8];
    const float* sm_b2  = (const float*)d_in[9];
    const float* sm_w3  = (const float*)d_in[10];
    const float* sm_b3  = (const float*)d_in[11];
    const float* sm_w5  = (const float*)d_in[12];
    const float* sm_b5  = (const float*)d_in[13];
    const float* sm_w6  = (const float*)d_in[14];
    const float* sm_b6  = (const float*)d_in[15];
    const float* on_w1  = (const float*)d_in[16];
    const float* on_b1  = (const float*)d_in[17];
    const float* on_w2  = (const float*)d_in[18];
    const float* on_b2  = (const float*)d_in[19];

    float* out = (float*)d_out;

    uint32_t *xh, *xl, *w1h, *w1l, *w3h, *w3l, *h1h, *h1l;
    float *partp, *sensp;
    cudaGetSymbolAddress((void**)&xh,  g_xh);
    cudaGetSymbolAddress((void**)&xl,  g_xl);
    cudaGetSymbolAddress((void**)&w1h, g_w1h);
    cudaGetSymbolAddress((void**)&w1l, g_w1l);
    cudaGetSymbolAddress((void**)&w3h, g_w3h);
    cudaGetSymbolAddress((void**)&w3l, g_w3l);
    cudaGetSymbolAddress((void**)&h1h, g_h1h);
    cudaGetSymbolAddress((void**)&h1l, g_h1l);
    cudaGetSymbolAddress((void**)&partp, g_part);
    cudaGetSymbolAddress((void**)&sensp, g_sens);

    const int DYN = 65536 + 512 + 8192;   // tiles + bias + wm2
    cudaFuncSetAttribute(gemm_hmma<3, 0>, cudaFuncAttributeMaxDynamicSharedMemorySize, DYN);
    cudaFuncSetAttribute(gemm_hmma<4, 1>, cudaFuncAttributeMaxDynamicSharedMemorySize, DYN);

    prep_w_kernel<<<(256 * 96 + 512 * 128 + 255) / 256, 256>>>(pm_w1, pm_w3);
    prep_x_kernel<<<BE * 96 / 256, 256>>>(sp);

    // GEMM A: h1 = leaky(x @ w1 + b1)  [BE x 256], K=192 (padded)
    gemm_hmma<3, 0><<<dim3(2, BE / 128), 256, DYN>>>(xh, xl, w1h, w1l, 96, pm_b1, nullptr);
    // GEMM B: fused leaky(h1 @ w3 + b3) @ wm2 -> partials, K=256
    gemm_hmma<4, 1><<<dim3(4, BE / 128), 256, DYN>>>(h1h, h1l, w3h, w3l, 128, pm_b3, pm_wm2);

    sensor_kernel<<<BATCH / 4, 256>>>(raw, sm_w2, sm_b2, sm_w3, sm_b3,
                                      sm_w5, sm_b5, sm_w6, sm_b6, sensp);
    enkf_kernel<<<BATCH, 256>>>(partp, pm_bm2, sensp, on_w1, on_b1, on_w2, on_b2,
                                out + O1_OFF, out + O2_OFF, out + O3_OFF,
                                out + O4_OFF, out + O5_OFF);
}

// round 5
// speedup vs baseline: 2.2073x; 1.0444x over previous
#include <cuda_runtime.h>
#include <cuda_bf16.h>
#include <cstdint>

#define BATCH 2048
#define ENS   32
#define DX    14
#define DZ    14
#define PM_IN 140
#define SM_IN 220
#define BE    (BATCH * ENS)

#define O1_OFF 0
#define O2_OFF (BATCH * ENS * DX)
#define O3_OFF (O2_OFF + BATCH * DX)
#define O4_OFF (O3_OFF + BATCH * DX)
#define O5_OFF (O4_OFF + BATCH * DZ)

// ---------------- scratch globals (uint32 = packed bf16 pair) ----------------
__device__ uint32_t g_xh [(size_t)BE * 96];    // x hi  [BE][192] bf16
__device__ uint32_t g_xl [(size_t)BE * 96];
__device__ uint32_t g_w1h[256 * 96];           // w1^T  [256][192]
__device__ uint32_t g_w1l[256 * 96];
__device__ uint32_t g_w3h[512 * 128];          // w3^T  [512][256]
__device__ uint32_t g_w3l[512 * 128];
__device__ uint32_t g_h1h[(size_t)BE * 128];   // h1    [BE][256]
__device__ uint32_t g_h1l[(size_t)BE * 128];
__device__ float    g_part[(size_t)8 * BE * DX];
__device__ float    g_sens[BATCH * DZ];

// ---------------- helpers ----------------
__device__ __forceinline__ uint32_t smem_u32(const void* p) {
    uint32_t a;
    asm("{ .reg .u64 t; cvta.to.shared.u64 t, %1; cvt.u32.u64 %0, t; }" : "=r"(a) : "l"(p));
    return a;
}
#define CP16(d, s) asm volatile("cp.async.cg.shared.global [%0], [%1], 16;" :: "r"(d), "l"(s))
#define CP_COMMIT() asm volatile("cp.async.commit_group;")
#define CP_WAIT0()  asm volatile("cp.async.wait_group 0;" ::: "memory")
#define CP_WAIT1()  asm volatile("cp.async.wait_group 1;" ::: "memory")

__device__ __forceinline__ void ldsm4(uint32_t (&r)[4], uint32_t addr) {
    asm volatile("ldmatrix.sync.aligned.m8n8.x4.shared.b16 {%0,%1,%2,%3}, [%4];"
                 : "=r"(r[0]), "=r"(r[1]), "=r"(r[2]), "=r"(r[3]) : "r"(addr));
}
__device__ __forceinline__ void mma_bf16(float (&d)[4], const uint32_t (&a)[4],
                                         uint32_t b0, uint32_t b1) {
    asm volatile(
        "mma.sync.aligned.m16n8k16.row.col.f32.bf16.bf16.f32 "
        "{%0,%1,%2,%3}, {%4,%5,%6,%7}, {%8,%9}, {%0,%1,%2,%3};"
        : "+f"(d[0]), "+f"(d[1]), "+f"(d[2]), "+f"(d[3])
        : "r"(a[0]), "r"(a[1]), "r"(a[2]), "r"(a[3]), "r"(b0), "r"(b1));
}
__device__ __forceinline__ void split2(float v0, float v1, uint32_t& hi, uint32_t& lo) {
    __nv_bfloat16 h0 = __float2bfloat16(v0), h1 = __float2bfloat16(v1);
    __nv_bfloat16 g0 = __float2bfloat16(v0 - __bfloat162float(h0));
    __nv_bfloat16 g1 = __float2bfloat16(v1 - __bfloat162float(h1));
    hi = (uint32_t)__bfloat16_as_ushort(h0) | ((uint32_t)__bfloat16_as_ushort(h1) << 16);
    lo = (uint32_t)__bfloat16_as_ushort(g0) | ((uint32_t)__bfloat16_as_ushort(g1) << 16);
}

// ---------------- prep: x -> hi/lo bf16, K padded to 192 ----------------
__global__ void __launch_bounds__(256)
prep_x_kernel(const float* __restrict__ x)
{
    int idx = blockIdx.x * 256 + threadIdx.x;   // BE*96
    int row = idx / 96, p = idx % 96, k = 2 * p;
    float v0 = (k < PM_IN) ? x[(size_t)row * PM_IN + k] : 0.f;
    float v1 = (k + 1 < PM_IN) ? x[(size_t)row * PM_IN + k + 1] : 0.f;
    uint32_t hi, lo;
    split2(v0, v1, hi, lo);
    g_xh[(size_t)row * 96 + p] = hi;
    g_xl[(size_t)row * 96 + p] = lo;
}

// ---------------- prep: weights transposed -> hi/lo bf16 ----------------
__global__ void __launch_bounds__(256)
prep_w_kernel(const float* __restrict__ w1, const float* __restrict__ w3)
{
    int idx = blockIdx.x * 256 + threadIdx.x;
    uint32_t hi, lo;
    if (idx < 256 * 96) {                        // w1 [140][256] -> [256][192]
        int n = idx / 96, p = idx % 96, k = 2 * p;
        float v0 = (k < PM_IN) ? w1[(size_t)k * 256 + n] : 0.f;
        float v1 = (k + 1 < PM_IN) ? w1[(size_t)(k + 1) * 256 + n] : 0.f;
        split2(v0, v1, hi, lo);
        g_w1h[idx] = hi; g_w1l[idx] = lo;
    } else if (idx < 256 * 96 + 512 * 128) {     // w3 [256][512] -> [512][256]
        int i2 = idx - 256 * 96;
        int n = i2 / 128, p = i2 % 128, k = 2 * p;
        split2(w3[(size_t)k * 512 + n], w3[(size_t)(k + 1) * 512 + n], hi, lo);
        g_w3h[i2] = hi; g_w3l[i2] = lo;
    }
}

// ---------------- HMMA split-bf16 GEMM, double-buffered cp.async ----------
// C-tile 128x128, BK=64, 8 warps (4x2), warp tile 32x64.
// SMEM: 2 stages x 4 tiles x 16KB = 128KB, + bias + wm2.
// EPI=0: h1 = leaky(acc+bias) split -> g_h1h/g_h1l
// EPI=1: fused wm2 projection -> g_part (8 slices)
template <int KCHUNKS, int EPI>
__global__ void __launch_bounds__(256, 1)
gemm_hmma(const uint32_t* __restrict__ Ah, const uint32_t* __restrict__ Al,
          const uint32_t* __restrict__ Bh, const uint32_t* __restrict__ Bl,
          int kstr,                             // row stride in uint32 (Kpad/2)
          const float* __restrict__ bias, const float* __restrict__ wm2)
{
    extern __shared__ char smem[];
    const uint32_t ub = smem_u32(smem);
    float* biasS = (float*)(smem + 131072);
    float* wm2s  = (float*)(smem + 131584);

    const int tid = threadIdx.x, wid = tid >> 5, lane = tid & 31;
    const int bn = blockIdx.x, bt = blockIdx.y;
    const int mw = (wid >> 1) * 32;              // warp m offset
    const int nw = (wid & 1) * 64;               // warp n offset

    if (tid < 128) biasS[tid] = bias[bn * 128 + tid];
    if (EPI == 1) {
        for (int i = tid; i < 128 * DX; i += 256) {
            int c = i / DX, m = i % DX;
            wm2s[c * 16 + m] = wm2[(size_t)(bn * 128 + c) * DX + m];
        }
    }

    // per-thread precomputed load coordinates (16 cp.async per thread/chunk)
    // i = tid + 256*q, q<16: t = i>>10, r = (i>>3)&127, c = i&7
    auto issue_load = [&](int stage, int kc) {
#pragma unroll
        for (int q = 0; q < 16; q++) {
            int i = tid + 256 * q;
            int t = i >> 10, r = (i >> 3) & 127, c = i & 7;
            const uint32_t* gp;
            int grow;
            if (t == 0)      { gp = Ah; grow = bt * 128 + r; }
            else if (t == 1) { gp = Al; grow = bt * 128 + r; }
            else if (t == 2) { gp = Bh; grow = bn * 128 + r; }
            else             { gp = Bl; grow = bn * 128 + r; }
            const uint32_t* src = gp + (size_t)grow * kstr + kc * 32 + c * 4;
            uint32_t dst = ub + stage * 65536 + t * 16384 + r * 128
                         + ((c * 16) ^ ((r & 7) << 4));
            CP16(dst, src);
        }
        CP_COMMIT();
    };

    float acc[2][8][4];
#pragma unroll
    for (int f = 0; f < 2; f++)
#pragma unroll
        for (int g = 0; g < 8; g++)
#pragma unroll
            for (int e = 0; e < 4; e++) acc[f][g][e] = 0.f;

    issue_load(0, 0);

#pragma unroll 1
    for (int kc = 0; kc < KCHUNKS; kc++) {
        const int s = kc & 1;
        if (kc + 1 < KCHUNKS) {
            issue_load(s ^ 1, kc + 1);
            CP_WAIT1();
        } else {
            CP_WAIT0();
        }
        __syncthreads();

        const uint32_t sb = ub + s * 65536;
#pragma unroll
        for (int k16 = 0; k16 < 4; k16++) {
            uint32_t ah[2][4], al[2][4];
#pragma unroll
            for (int f = 0; f < 2; f++) {
                int mrow = mw + f * 16 + (lane & 15);
                int cb = k16 * 32 + ((lane >> 4) << 4);
                uint32_t off = mrow * 128 + (cb ^ ((mrow & 7) << 4));
                ldsm4(ah[f], sb + off);
                ldsm4(al[f], sb + 16384 + off);
            }
            uint32_t bh[4][4], bl[4][4];
#pragma unroll
            for (int g = 0; g < 4; g++) {
                int nrow = nw + g * 16 + ((lane >> 4) << 3) + (lane & 7);
                int cb = k16 * 32 + (((lane >> 3) & 1) << 4);
                uint32_t off = nrow * 128 + (cb ^ ((nrow & 7) << 4));
                ldsm4(bh[g], sb + 32768 + off);
                ldsm4(bl[g], sb + 49152 + off);
            }
#pragma unroll
            for (int f = 0; f < 2; f++)
#pragma unroll
                for (int g = 0; g < 4; g++) {
                    mma_bf16(acc[f][2 * g],     ah[f], bh[g][0], bh[g][1]);
                    mma_bf16(acc[f][2 * g],     ah[f], bl[g][0], bl[g][1]);
                    mma_bf16(acc[f][2 * g],     al[f], bh[g][0], bh[g][1]);
                    mma_bf16(acc[f][2 * g + 1], ah[f], bh[g][2], bh[g][3]);
                    mma_bf16(acc[f][2 * g + 1], ah[f], bl[g][2], bl[g][3]);
                    mma_bf16(acc[f][2 * g + 1], al[f], bh[g][2], bh[g][3]);
                }
        }
        __syncthreads();   // all warps done reading stage s before it is refilled
    }

    if (EPI == 0) {
        // h1 = leaky(acc + bias), split to hi/lo, packed pair writes
#pragma unroll
        for (int f = 0; f < 2; f++) {
            int row0 = bt * 128 + mw + f * 16 + (lane >> 2);
#pragma unroll
            for (int nf = 0; nf < 8; nf++) {
                int col = nw + nf * 8 + 2 * (lane & 3);
                float b0 = biasS[col], b1 = biasS[col + 1];
                float v0 = acc[f][nf][0] + b0, v1 = acc[f][nf][1] + b1;
                float v2 = acc[f][nf][2] + b0, v3 = acc[f][nf][3] + b1;
                v0 = v0 >= 0.f ? v0 : 0.01f * v0;
                v1 = v1 >= 0.f ? v1 : 0.01f * v1;
                v2 = v2 >= 0.f ? v2 : 0.01f * v2;
                v3 = v3 >= 0.f ? v3 : 0.01f * v3;
                uint32_t hi, lo;
                int gcol = bn * 128 + col;
                split2(v0, v1, hi, lo);
                g_h1h[(size_t)row0 * 128 + gcol / 2] = hi;
                g_h1l[(size_t)row0 * 128 + gcol / 2] = lo;
                split2(v2, v3, hi, lo);
                g_h1h[(size_t)(row0 + 8) * 128 + gcol / 2] = hi;
                g_h1l[(size_t)(row0 + 8) * 128 + gcol / 2] = lo;
            }
        }
    } else {
        // fused projection: proj[slot][m] = sum_c leaky(acc+b3)[c] * wm2[c][m]
        float proj[4][DX];
#pragma unroll
        for (int s = 0; s < 4; s++)
#pragma unroll
            for (int m = 0; m < DX; m++) proj[s][m] = 0.f;
#pragma unroll
        for (int f = 0; f < 2; f++)
#pragma unroll
            for (int nf = 0; nf < 8; nf++) {
                int col = nw + nf * 8 + 2 * (lane & 3);
#pragma unroll
                for (int e = 0; e < 2; e++) {
                    int c = col + e;
                    float b = biasS[c];
                    float v0 = acc[f][nf][e] + b;
                    float v1 = acc[f][nf][2 + e] + b;
                    v0 = v0 >= 0.f ? v0 : 0.01f * v0;
                    v1 = v1 >= 0.f ? v1 : 0.01f * v1;
                    const float* wr = wm2s + c * 16;
#pragma unroll
                    for (int m = 0; m < DX; m++) {
                        float wv = wr[m];
                        proj[2 * f][m]     += v0 * wv;
                        proj[2 * f + 1][m] += v1 * wv;
                    }
                }
            }
#pragma unroll
        for (int s = 0; s < 4; s++)
#pragma unroll
            for (int m = 0; m < DX; m++) {
                proj[s][m] += __shfl_xor_sync(0xFFFFFFFFu, proj[s][m], 1);
                proj[s][m] += __shfl_xor_sync(0xFFFFFFFFu, proj[s][m], 2);
            }
        if ((lane & 3) == 0) {
            int slice = bn * 2 + (wid & 1);
#pragma unroll
            for (int s = 0; s < 4; s++) {
                int row = bt * 128 + mw + (s >> 1) * 16 + (lane >> 2) + (s & 1) * 8;
                float* dst = g_part + ((size_t)slice * BE + row) * DX;
#pragma unroll
                for (int m = 0; m < DX; m++) dst[m] = proj[s][m];
            }
        }
    }
}

// ---------------- sensor MLP on 2048 distinct rows ----------------
__global__ void __launch_bounds__(256)
sensor_kernel(const float* __restrict__ raw,
              const float* __restrict__ w2, const float* __restrict__ b2,
              const float* __restrict__ w3, const float* __restrict__ b3,
              const float* __restrict__ w5, const float* __restrict__ b5,
              const float* __restrict__ w6, const float* __restrict__ b6,
              float* __restrict__ sens)
{
    __shared__ float s[4][SM_IN], h1[4][256], h2[4][256], h3[4][64];
    const int tid = threadIdx.x;
    const int row0 = blockIdx.x * 4;

    for (int i = tid; i < 4 * SM_IN; i += 256)
        s[i / SM_IN][i % SM_IN] = raw[(size_t)(row0 + i / SM_IN) * SM_IN + i % SM_IN];
    __syncthreads();
    {
        float acc[4];
#pragma unroll
        for (int r = 0; r < 4; r++) acc[r] = b2[tid];
        for (int k = 0; k < SM_IN; k++) {
            float w = w2[k * 256 + tid];
#pragma unroll
            for (int r = 0; r < 4; r++) acc[r] += s[r][k] * w;
        }
#pragma unroll
        for (int r = 0; r < 4; r++) h1[r][tid] = acc[r] >= 0.f ? acc[r] : 0.01f * acc[r];
    }
    __syncthreads();
    {
        float acc[4];
#pragma unroll
        for (int r = 0; r < 4; r++) acc[r] = b3[tid];
        for (int k = 0; k < 256; k++) {
            float w = w3[k * 256 + tid];
#pragma unroll
            for (int r = 0; r < 4; r++) acc[r] += h1[r][k] * w;
        }
#pragma unroll
        for (int r = 0; r < 4; r++) h2[r][tid] = acc[r] >= 0.f ? acc[r] : 0.01f * acc[r];
    }
    __syncthreads();
    if (tid < 64) {
        float acc[4];
#pragma unroll
        for (int r = 0; r < 4; r++) acc[r] = b5[tid];
        for (int k = 0; k < 256; k++) {
            float w = w5[k * 64 + tid];
#pragma unroll
            for (int r = 0; r < 4; r++) acc[r] += h2[r][k] * w;
        }
#pragma unroll
        for (int r = 0; r < 4; r++) h3[r][tid] = acc[r] >= 0.f ? acc[r] : 0.01f * acc[r];
    }
    __syncthreads();
    if (tid < DZ) {
        float acc[4];
#pragma unroll
        for (int r = 0; r < 4; r++) acc[r] = b6[tid];
        for (int k = 0; k < 64; k++) {
            float w = w6[k * DZ + tid];
#pragma unroll
            for (int r = 0; r < 4; r++) acc[r] += h3[r][k] * w;
        }
#pragma unroll
        for (int r = 0; r < 4; r++) sens[(size_t)(row0 + r) * DZ + tid] = acc[r];
    }
}

// ---------------- EnKF per batch element ----------------
__global__ void __launch_bounds__(256)
enkf_kernel(const float* __restrict__ part, const float* __restrict__ pm_bm2,
            const float* __restrict__ sens,
            const float* __restrict__ on_w1, const float* __restrict__ on_b1,
            const float* __restrict__ on_w2, const float* __restrict__ on_b2,
            float* __restrict__ out1, float* __restrict__ out2,
            float* __restrict__ out3, float* __restrict__ out4,
            float* __restrict__ out5)
{
    const int b = blockIdx.x, tid = threadIdx.x;
    __shared__ float pred[ENS][DX], ez[ENS][DZ], Am[ENS][DX], corr[ENS][DX];
    __shared__ float sm[DX], zm[DZ], rdiag[DZ], hid[32];
    __shared__ float Mm[DX][DX], Km[DX][DZ], aug[DX][2 * DX], fac[DX];

    for (int i = tid; i < ENS * DX; i += 256) {
        int e = i / DX, j = i % DX;
        size_t row = (size_t)b * ENS + e;
        float p = pm_bm2[j];
#pragma unroll
        for (int q = 0; q < 8; q++) p += part[((size_t)q * BE + row) * DX + j];
        pred[e][j] = p;
    }
    for (int i = tid; i < ENS * DZ; i += 256) {
        int e = i / DZ, j = i % DZ;
        int src = (b * ENS + e) % BATCH;
        float v = sens[src * DZ + j];
        ez[e][j] = v;
        out5[(size_t)(b * ENS + e) * DZ + j] = v;
    }
    __syncthreads();
    if (tid < DX) {
        float s1 = 0.f, s2 = 0.f;
        for (int e = 0; e < ENS; e++) { s1 += pred[e][tid]; s2 += ez[e][tid]; }
        float m1 = s1 * (1.f / ENS), m2 = s2 * (1.f / ENS);
        sm[tid] = m1; zm[tid] = m2;
        out3[b * DX + tid] = m1;
        out4[b * DZ + tid] = m2;
    }
    __syncthreads();
    if (tid < 32) {
        float a = on_b1[tid];
        for (int i = 0; i < DZ; i++) a += zm[i] * on_w1[i * 32 + tid];
        hid[tid] = a > 0.f ? a : 0.f;
    }
    __syncthreads();
    if (tid < DZ) {
        float a = on_b2[tid];
        for (int j = 0; j < 32; j++) a += hid[j] * on_w2[j * DZ + tid];
        a += 0.001f;
        rdiag[tid] = a * a + 0.038729833f;
    }
    for (int i = tid; i < ENS * DX; i += 256)
        Am[i / DX][i % DX] = pred[i / DX][i % DX] - sm[i % DX];
    __syncthreads();
    if (tid < DX * DX) {
        int i = tid / DX, j = tid % DX;
        float s = 0.f;
        for (int e = 0; e < ENS; e++) s += Am[e][i] * Am[e][j];
        float m = s * (1.f / (ENS - 1));
        Mm[i][j] = m;
        aug[i][j] = m + (i == j ? rdiag[i] : 0.f);
        aug[i][DX + j] = (i == j) ? 1.f : 0.f;
    }
    __syncthreads();
    for (int p = 0; p < DX; p++) {
        float pv = aug[p][p];
        __syncthreads();
        if (tid < 2 * DX) aug[p][tid] *= (1.f / pv);
        if (tid < DX) fac[tid] = (tid == p) ? 0.f : aug[tid][p];
        __syncthreads();
        for (int t = tid; t < DX * 2 * DX; t += 256) {
            int rr = t / (2 * DX), c = t % (2 * DX);
            if (rr != p) aug[rr][c] -= fac[rr] * aug[p][c];
        }
        __syncthreads();
    }
    if (tid < DX * DX) {
        int i = tid / DX, j = tid % DX;
        float s = 0.f;
        for (int k = 0; k < DX; k++) s += Mm[i][k] * aug[k][DX + j];
        Km[i][j] = s;
    }
    __syncthreads();
    for (int t = tid; t < ENS * DX; t += 256) {
        int e = t / DX, i = t % DX;
        float s = pred[e][i];
        for (int j = 0; j < DZ; j++) s += Km[i][j] * (ez[e][j] - pred[e][j]);
        corr[e][i] = s;
        out1[(size_t)(b * ENS + e) * DX + i] = s;
    }
    __syncthreads();
    if (tid < DX) {
        float s = 0.f;
        for (int e = 0; e < ENS; e++) s += corr[e][tid];
        out2[b * DX + tid] = s * (1.f / ENS);
    }
}

// ---------------- launcher ----------------
extern "C" void kernel_launch(void* const* d_in, const int* in_sizes, int n_in,
                              void* d_out, int out_size)
{
    const float* raw    = (const float*)d_in[0];
    const float* sp     = (const float*)d_in[1];
    const float* pm_w1  = (const float*)d_in[2];
    const float* pm_b1  = (const float*)d_in[3];
    const float* pm_w3  = (const float*)d_in[4];
    const float* pm_b3  = (const float*)d_in[5];
    const float* pm_wm2 = (const float*)d_in[6];
    const float* pm_bm2 = (const float*)d_in[7];
    const float* sm_w2  = (const float*)d_in[8];
    const float* sm_b2  = (const float*)d_in[9];
    const float* sm_w3  = (const float*)d_in[10];
    const float* sm_b3  = (const float*)d_in[11];
    const float* sm_w5  = (const float*)d_in[12];
    const float* sm_b5  = (const float*)d_in[13];
    const float* sm_w6  = (const float*)d_in[14];
    const float* sm_b6  = (const float*)d_in[15];
    const float* on_w1  = (const float*)d_in[16];
    const float* on_b1  = (const float*)d_in[17];
    const float* on_w2  = (const float*)d_in[18];
    const float* on_b2  = (const float*)d_in[19];

    float* out = (float*)d_out;

    uint32_t *xh, *xl, *w1h, *w1l, *w3h, *w3l, *h1h, *h1l;
    float *partp, *sensp;
    cudaGetSymbolAddress((void**)&xh,  g_xh);
    cudaGetSymbolAddress((void**)&xl,  g_xl);
    cudaGetSymbolAddress((void**)&w1h, g_w1h);
    cudaGetSymbolAddress((void**)&w1l, g_w1l);
    cudaGetSymbolAddress((void**)&w3h, g_w3h);
    cudaGetSymbolAddress((void**)&w3l, g_w3l);
    cudaGetSymbolAddress((void**)&h1h, g_h1h);
    cudaGetSymbolAddress((void**)&h1l, g_h1l);
    cudaGetSymbolAddress((void**)&partp, g_part);
    cudaGetSymbolAddress((void**)&sensp, g_sens);

    const int DYN = 131072 + 512 + 8192;   // 2-stage tiles + bias + wm2
    cudaFuncSetAttribute(gemm_hmma<3, 0>, cudaFuncAttributeMaxDynamicSharedMemorySize, DYN);
    cudaFuncSetAttribute(gemm_hmma<4, 1>, cudaFuncAttributeMaxDynamicSharedMemorySize, DYN);

    prep_w_kernel<<<(256 * 96 + 512 * 128 + 255) / 256, 256>>>(pm_w1, pm_w3);
    prep_x_kernel<<<BE * 96 / 256, 256>>>(sp);

    // GEMM A: h1 = leaky(x @ w1 + b1)  [BE x 256], K=192 (padded)
    gemm_hmma<3, 0><<<dim3(2, BE / 128), 256, DYN>>>(xh, xl, w1h, w1l, 96, pm_b1, nullptr);
    // GEMM B: fused leaky(h1 @ w3 + b3) @ wm2 -> partials, K=256
    gemm_hmma<4, 1><<<dim3(4, BE / 128), 256, DYN>>>(h1h, h1l, w3h, w3l, 128, pm_b3, pm_wm2);

    sensor_kernel<<<BATCH / 4, 256>>>(raw, sm_w2, sm_b2, sm_w3, sm_b3,
                                      sm_w5, sm_b5, sm_w6, sm_b6, sensp);
    enkf_kernel<<<BATCH, 256>>>(partp, pm_bm2, sensp, on_w1, on_b1, on_w2, on_b2,
                                out + O1_OFF, out + O2_OFF, out + O3_OFF,
                                out + O4_OFF, out + O5_OFF);
}